// round 16
// baseline (speedup 1.0000x reference)
#include <cuda_runtime.h>
#include <cuda_fp16.h>
#include <cstdint>

// ---------------------------------------------------------------------------
// MultiHeadSelfAttention: B=128,H=128,F=8,D=200, nh=10, hd=20
// Projections: mma.sync fp16 3-pass split GEMM; epilogue emits fp16 hi/lo
// Q/K/V (lo x2048) or fp32 (final out). Attention on tensor cores, block =
// (i, h, q-half): 64 q-rows, 256 thr, 3 blocks/SM. scale/ln2 folded into Wk.
// ---------------------------------------------------------------------------

typedef unsigned long long u64;

#define SZH (131072L * 200)

__device__ float  g_ctx[131072L * 200];
__device__ __half g_h6[6 * 131072L * 200];       // qh,ql,kh,kl,vh,vl
__device__ __half g_whi[3][208 * 256];
__device__ __half g_wlo[3][208 * 256];

#define LO_SCALE 2048.0f
#define LO_INV   (1.0f / 2048.0f)

// =========================== helpers =======================================
__device__ __forceinline__ void mma_f32acc(float* d, const uint32_t* a,
                                           uint32_t b0, uint32_t b1) {
    asm volatile(
        "mma.sync.aligned.m16n8k16.row.col.f32.f16.f16.f32 "
        "{%0,%1,%2,%3}, {%4,%5,%6,%7}, {%8,%9}, {%0,%1,%2,%3};"
        : "+f"(d[0]), "+f"(d[1]), "+f"(d[2]), "+f"(d[3])
        : "r"(a[0]), "r"(a[1]), "r"(a[2]), "r"(a[3]), "r"(b0), "r"(b1));
}
__device__ __forceinline__ void mma_f16acc(uint32_t* d, const uint32_t* a,
                                           uint32_t b0, uint32_t b1) {
    asm volatile(
        "mma.sync.aligned.m16n8k16.row.col.f16.f16.f16.f16 "
        "{%0,%1}, {%2,%3,%4,%5}, {%6,%7}, {%0,%1};"
        : "+r"(d[0]), "+r"(d[1])
        : "r"(a[0]), "r"(a[1]), "r"(a[2]), "r"(a[3]), "r"(b0), "r"(b1));
}
__device__ __forceinline__ void ldsm_x4(uint32_t* r, uint32_t addr) {
    asm volatile("ldmatrix.sync.aligned.m8n8.x4.shared.b16 {%0,%1,%2,%3}, [%4];"
        : "=r"(r[0]), "=r"(r[1]), "=r"(r[2]), "=r"(r[3]) : "r"(addr));
}
__device__ __forceinline__ void ldsm_x2(uint32_t* r, uint32_t addr) {
    asm volatile("ldmatrix.sync.aligned.m8n8.x2.shared.b16 {%0,%1}, [%2];"
        : "=r"(r[0]), "=r"(r[1]) : "r"(addr));
}
__device__ __forceinline__ void ldsm_x4_t(uint32_t* r, uint32_t addr) {
    asm volatile("ldmatrix.sync.aligned.m8n8.x4.trans.shared.b16 {%0,%1,%2,%3}, [%4];"
        : "=r"(r[0]), "=r"(r[1]), "=r"(r[2]), "=r"(r[3]) : "r"(addr));
}
__device__ __forceinline__ void ldsm_x2_t(uint32_t* r, uint32_t addr) {
    asm volatile("ldmatrix.sync.aligned.m8n8.x2.trans.shared.b16 {%0,%1}, [%2];"
        : "=r"(r[0]), "=r"(r[1]) : "r"(addr));
}
__device__ __forceinline__ uint32_t smem_u32(const void* p) {
    uint32_t a;
    asm("{ .reg .u64 t; cvta.to.shared.u64 t, %1; cvt.u32.u64 %0, t; }"
        : "=r"(a) : "l"(p));
    return a;
}
__device__ __forceinline__ void cp16(uint32_t dst, const void* src) {
    asm volatile("cp.async.ca.shared.global [%0], [%1], 16;"
                 :: "r"(dst), "l"(src) : "memory");
}
#define CP_COMMIT() asm volatile("cp.async.commit_group;" ::: "memory")
#define CP_WAIT0()  asm volatile("cp.async.wait_group 0;" ::: "memory")
__device__ __forceinline__ float ex2(float x) {
    float r; asm("ex2.approx.f32 %0, %1;" : "=f"(r) : "f"(x)); return r;
}

// ====== W{q,k,v} -> Wt[208][256] fp16 hi/lo (transpose+split), one launch ===
__global__ __launch_bounds__(256)
void conv_wt3(const float* __restrict__ wq, const float* __restrict__ wk,
              const float* __restrict__ wv, __half* __restrict__ hi,
              __half* __restrict__ lo) {
    const int w = blockIdx.y;
    const float* W = (w == 0) ? wq : (w == 1) ? wk : wv;
    const float s2 = 0.22360679774997896f / 0.6931471805599453f;
    int idx = blockIdx.x * 256 + threadIdx.x;     // over 208*256
    int n = idx >> 8, k = idx & 255;
    float v = (n < 200 && k < 200) ? W[k * 200 + n] : 0.f;
    if (w == 1) v *= s2;
    __half h = __float2half_rn(v);
    float r = (v - __half2float(h)) * LO_SCALE;
    hi[(long)w * (208 * 256) + idx] = h;
    lo[(long)w * (208 * 256) + idx] = __float2half_rn(r);
}

// ============ mma.sync fp16-split GEMM: 64x208 block, 2 blocks/SM ==========
#define AH_OFF 0
#define AL_OFF 9216
#define BH_OFF 18432
#define BL_OFF 48384
#define GEMM_SMEM 78336

__device__ __forceinline__ void load_a_chunk(const float* __restrict__ A,
                                             long row0, int tid, int kb,
                                             float4* abuf) {
    int r = tid >> 2, u4 = tid & 3;
    const float* ap = A + (row0 + r) * 200;
    #pragma unroll
    for (int q = 0; q < 4; q++) {
        int col0 = kb + u4 * 16 + q * 4;
        abuf[q] = (col0 < 200) ? *(const float4*)(ap + col0)
                               : make_float4(0.f, 0.f, 0.f, 0.f);
    }
}

__device__ __forceinline__ void conv_a_to_smem(char* smem, int tid,
                                               const float4* abuf) {
    int r = tid >> 2, u4 = tid & 3;
    char* ahp = smem + AH_OFF + r * 144 + u4 * 32;
    char* alp = smem + AL_OFF + r * 144 + u4 * 32;
    #pragma unroll
    for (int q = 0; q < 4; q++) {
        float4 v = abuf[q];
        __half2 h01 = __floats2half2_rn(v.x, v.y);
        __half2 h23 = __floats2half2_rn(v.z, v.w);
        float rx = (v.x - __low2float(h01))  * LO_SCALE;
        float ry = (v.y - __high2float(h01)) * LO_SCALE;
        float rz = (v.z - __low2float(h23))  * LO_SCALE;
        float rw = (v.w - __high2float(h23)) * LO_SCALE;
        __half2 l01 = __floats2half2_rn(rx, ry);
        __half2 l23 = __floats2half2_rn(rz, rw);
        *(uint32_t*)(ahp + q * 8)     = *(uint32_t*)&h01;
        *(uint32_t*)(ahp + q * 8 + 4) = *(uint32_t*)&h23;
        *(uint32_t*)(alp + q * 8)     = *(uint32_t*)&l01;
        *(uint32_t*)(alp + q * 8 + 4) = *(uint32_t*)&l23;
    }
}

__device__ __forceinline__ void issue_b_cpasync(uint32_t sbase, int tid,
                                                const __half* Bh,
                                                const __half* Bl, int kb) {
    #pragma unroll
    for (int i = 0; i < 13; i++) {
        int e = tid + i * 256;            // 0..3327
        int buf = e >= 1664;
        int e2 = buf ? e - 1664 : e;
        int n = e2 >> 3, u = e2 & 7;
        const __half* src = (buf ? Bl : Bh) + n * 256 + kb + u * 8;
        uint32_t dst = sbase + (buf ? BL_OFF : BH_OFF) + n * 144 + u * 16;
        cp16(dst, src);
    }
    CP_COMMIT();
}

__device__ __forceinline__ void mma_nt(float* accf, uint32_t* accc,
                                       const uint32_t* ah, const uint32_t* al,
                                       uint32_t bh0, uint32_t bh1,
                                       uint32_t bl0, uint32_t bl1) {
    mma_f32acc(accf, ah, bh0, bh1);
    mma_f16acc(accc, ah, bl0, bl1);
    mma_f16acc(accc, al, bh0, bh1);
}

// mode 0: write fp32 C. mode 1: write fp16 hi/lo (lo x2048) to Ch/Cl.
__global__ __launch_bounds__(256, 2)
void gemm_mma(const float* __restrict__ A,
              const __half* __restrict__ Bh,
              const __half* __restrict__ Bl,
              float* __restrict__ C,
              __half* __restrict__ Ch, __half* __restrict__ Cl,
              int mode) {
    extern __shared__ char smem[];
    const uint32_t sbase = smem_u32(smem);
    const int tid  = threadIdx.x;
    const int wid  = tid >> 5, lane = tid & 31;
    const int wm   = wid >> 1, wn = wid & 1;     // 4(M) x 2(N)
    const int g    = lane >> 2, t = lane & 3;
    const long row0 = (long)blockIdx.x * 64;

    const uint32_t aA = sbase + AH_OFF
        + (uint32_t)(wm * 16 + (lane & 15)) * 144 + (uint32_t)(lane >> 4) * 16;
    const uint32_t aB = sbase + BH_OFF
        + (uint32_t)(wn * 104 + (lane & 7) + ((lane >> 4) & 1) * 8) * 144
        + (uint32_t)((lane >> 3) & 1) * 16;

    float    accf[13][4];
    uint32_t accc[13][2];
    #pragma unroll
    for (int nt = 0; nt < 13; nt++) {
        accf[nt][0] = accf[nt][1] = accf[nt][2] = accf[nt][3] = 0.f;
        accc[nt][0] = accc[nt][1] = 0u;
    }

    float4 abuf[4];
    load_a_chunk(A, row0, tid, 0, abuf);
    issue_b_cpasync(sbase, tid, Bh, Bl, 0);
    conv_a_to_smem(smem, tid, abuf);
    CP_WAIT0();
    __syncthreads();

    #pragma unroll 1
    for (int c = 0; c < 4; c++) {
        if (c < 3) load_a_chunk(A, row0, tid, (c + 1) * 64, abuf);

        const int nst = (c < 3) ? 4 : 1;
        #pragma unroll 1
        for (int ks = 0; ks < nst; ks++) {
            const uint32_t ao = (uint32_t)ks * 32;
            uint32_t ah[4], al[4];
            ldsm_x4(ah, aA + ao);
            ldsm_x4(al, aA + 9216 + ao);
            #pragma unroll
            for (int p = 0; p < 6; p++) {
                uint32_t bh[4], bl[4];
                ldsm_x4(bh, aB + p * 2304 + ao);
                ldsm_x4(bl, aB + p * 2304 + 29952 + ao);
                mma_nt(accf[2 * p],     accc[2 * p],     ah, al,
                       bh[0], bh[1], bl[0], bl[1]);
                mma_nt(accf[2 * p + 1], accc[2 * p + 1], ah, al,
                       bh[2], bh[3], bl[2], bl[3]);
            }
            {
                uint32_t bh[2], bl[2];
                ldsm_x2(bh, aB + 13824 + ao);
                ldsm_x2(bl, aB + 13824 + 29952 + ao);
                mma_nt(accf[12], accc[12], ah, al,
                       bh[0], bh[1], bl[0], bl[1]);
            }
        }

        if (c < 3) {
            __syncthreads();
            issue_b_cpasync(sbase, tid, Bh, Bl, (c + 1) * 64);
            conv_a_to_smem(smem, tid, abuf);
            CP_WAIT0();
            __syncthreads();
        }
    }

    long r0 = row0 + wm * 16 + g;
    #pragma unroll
    for (int nt = 0; nt < 13; nt++) {
        int col = wn * 104 + nt * 8 + t * 2;
        if (col < 200) {
            __half2 h0 = *(__half2*)&accc[nt][0];
            __half2 h1 = *(__half2*)&accc[nt][1];
            float v0 = accf[nt][0] + __low2float(h0)  * LO_INV;
            float v1 = accf[nt][1] + __high2float(h0) * LO_INV;
            float v2 = accf[nt][2] + __low2float(h1)  * LO_INV;
            float v3 = accf[nt][3] + __high2float(h1) * LO_INV;
            if (mode == 0) {
                *(float2*)(C + r0 * 200 + col)       = make_float2(v0, v1);
                *(float2*)(C + (r0 + 8) * 200 + col) = make_float2(v2, v3);
            } else {
                __half2 hh0 = __floats2half2_rn(v0, v1);
                __half2 hh1 = __floats2half2_rn(v2, v3);
                __half2 ll0 = __floats2half2_rn(
                    (v0 - __low2float(hh0))  * LO_SCALE,
                    (v1 - __high2float(hh0)) * LO_SCALE);
                __half2 ll1 = __floats2half2_rn(
                    (v2 - __low2float(hh1))  * LO_SCALE,
                    (v3 - __high2float(hh1)) * LO_SCALE);
                *(__half2*)(Ch + r0 * 200 + col)       = hh0;
                *(__half2*)(Ch + (r0 + 8) * 200 + col) = hh1;
                *(__half2*)(Cl + r0 * 200 + col)       = ll0;
                *(__half2*)(Cl + (r0 + 8) * 200 + col) = ll1;
            }
        }
    }
}

// ============== Tensor-core attention per (i, h, q-half) ====================
// 256 threads = 8 warps; warp = (qr0 = (wid>>1)*16 of 64 q-rows) x (key-half).
// smem: Q hi/lo 2x5120, K/V hi/lo 4x10240, P 64x272, ps 2x64 f32.
// ctx-partial buffer reuses the Q region (dead after QK).
#define A_QH 0
#define A_QL 5120
#define A_KH 10240
#define A_KL 20480
#define A_VH 30720
#define A_VL 40960
#define A_P  51200
#define A_PS 68608
#define ATT_SMEM 69120

__global__ __launch_bounds__(256, 3)
void attn_mma(const __half* __restrict__ H6, float* __restrict__ AW,
              float* __restrict__ CTX) {
    extern __shared__ char smem[];
    const uint32_t sb = smem_u32(smem);
    const int tid  = threadIdx.x;
    const int lane = tid & 31, wid = tid >> 5;
    const int g = lane >> 2, t = lane & 3;
    const int qr0 = (wid >> 1) * 16;
    const int th  = wid & 1;
    const long rb = (long)blockIdx.x * 128;
    const int hoff = blockIdx.y * 20;
    const long qrow0 = rb + blockIdx.z * 64;

    // ---- load Q (64 rows) + K/V (128 rows) hi/lo slices ----
    #pragma unroll
    for (int rr = 0; rr < 3; rr++) {
        int tau = tid + rr * 256;
        if (tau < 640) {
            const u64* src;
            u64* dst;
            if (tau < 128) {
                int buf = tau >> 6, r = tau & 63;        // QH, QL
                src = (const u64*)(H6 + (long)buf * SZH + (qrow0 + r) * 200 + hoff);
                dst = (u64*)(smem + buf * 5120 + r * 80);
            } else {
                int tau2 = tau - 128;
                int buf = tau2 >> 7, r = tau2 & 127;     // KH,KL,VH,VL
                src = (const u64*)(H6 + (long)(buf + 2) * SZH + (rb + r) * 200 + hoff);
                dst = (u64*)(smem + A_KH + buf * 10240 + r * 80);
            }
            dst[0] = src[0]; dst[1] = src[1]; dst[2] = src[2];
            dst[3] = src[3]; dst[4] = src[4];
            dst[5] = 0; dst[6] = 0; dst[7] = 0;          // zero-pad d20..31
        }
    }
    __syncthreads();

    const uint32_t rowsel = ((lane >> 3) & 1) * 8 + (lane & 7);

    // ---------------- QK^T: 3-pass fp16 split ----------------
    const uint32_t aQ = sb + A_QH + (qr0 + rowsel) * 80 + (lane >> 4) * 16;
    const uint32_t bK = sb + A_KH
        + (th * 64 + ((lane >> 4) & 1) * 8 + (lane & 7)) * 80
        + ((lane >> 3) & 1) * 16;

    float    accf[8][4];
    uint32_t corr[8][2];
    #pragma unroll
    for (int nt = 0; nt < 8; nt++) {
        accf[nt][0] = accf[nt][1] = accf[nt][2] = accf[nt][3] = 0.f;
        corr[nt][0] = corr[nt][1] = 0u;
    }
    #pragma unroll
    for (int ks = 0; ks < 2; ks++) {
        uint32_t ah[4], al[4];
        ldsm_x4(ah, aQ + ks * 32);
        ldsm_x4(al, aQ + 5120 + ks * 32);
        #pragma unroll
        for (int p = 0; p < 4; p++) {
            uint32_t bh[4], bl[4];
            ldsm_x4(bh, bK + p * 1280 + ks * 32);
            ldsm_x4(bl, bK + 10240 + p * 1280 + ks * 32);
            mma_f32acc(accf[2 * p],     ah, bh[0], bh[1]);
            mma_f16acc(corr[2 * p],     ah, bl[0], bl[1]);
            mma_f16acc(corr[2 * p],     al, bh[0], bh[1]);
            mma_f32acc(accf[2 * p + 1], ah, bh[2], bh[3]);
            mma_f16acc(corr[2 * p + 1], ah, bl[2], bl[3]);
            mma_f16acc(corr[2 * p + 1], al, bh[2], bh[3]);
        }
    }

    // ---------------- exp, P->smem(fp16), row sums ----------------
    float sum_a = 0.f, sum_b = 0.f;
    char* pst = smem + A_P + (qr0 + g) * 272 + (th * 64 + 2 * t) * 2;
    #pragma unroll
    for (int nt = 0; nt < 8; nt++) {
        __half2 c0 = *(__half2*)&corr[nt][0];
        __half2 c1 = *(__half2*)&corr[nt][1];
        float e0 = ex2(accf[nt][0] + __low2float(c0)  * LO_INV);
        float e1 = ex2(accf[nt][1] + __high2float(c0) * LO_INV);
        float e2 = ex2(accf[nt][2] + __low2float(c1)  * LO_INV);
        float e3 = ex2(accf[nt][3] + __high2float(c1) * LO_INV);
        sum_a += e0 + e1; sum_b += e2 + e3;
        __half2 p01 = __floats2half2_rn(e0, e1);
        __half2 p23 = __floats2half2_rn(e2, e3);
        *(uint32_t*)(pst + nt * 16)           = *(uint32_t*)&p01;
        *(uint32_t*)(pst + 8 * 272 + nt * 16) = *(uint32_t*)&p23;
    }
    sum_a += __shfl_xor_sync(0xffffffffu, sum_a, 1);
    sum_a += __shfl_xor_sync(0xffffffffu, sum_a, 2);
    sum_b += __shfl_xor_sync(0xffffffffu, sum_b, 1);
    sum_b += __shfl_xor_sync(0xffffffffu, sum_b, 2);
    float* ps = (float*)(smem + A_PS);
    if (t == 0) {
        ps[th * 64 + qr0 + g]     = sum_a;
        ps[th * 64 + qr0 + 8 + g] = sum_b;
    }
    __syncthreads();

    // ---------------- AW write: cooperative, coalesced ----------------
    {
        float4* aw4 = (float4*)(AW + ((long)blockIdx.x * 10 + blockIdx.y) * 16384
                                   + (long)blockIdx.z * 8192);
        #pragma unroll
        for (int e0 = 0; e0 < 8; e0++) {
            int e = tid + e0 * 256;
            int s = e >> 5, l = e & 31;
            uint32_t pv[2];
            *(u64*)pv = *(const u64*)(smem + A_P + s * 272 + l * 8);
            __half2 p01 = *(__half2*)&pv[0];
            __half2 p23 = *(__half2*)&pv[1];
            float inv = 1.0f / (ps[s] + ps[64 + s]);
            aw4[e] = make_float4(__low2float(p01) * inv, __high2float(p01) * inv,
                                 __low2float(p23) * inv, __high2float(p23) * inv);
        }
    }

    // ---------------- AV: P(fp16) @ (Vh + Vl/2048) ----------------
    float oh[3][4], ol[3][4];
    #pragma unroll
    for (int nt = 0; nt < 3; nt++) {
        oh[nt][0] = oh[nt][1] = oh[nt][2] = oh[nt][3] = 0.f;
        ol[nt][0] = ol[nt][1] = ol[nt][2] = ol[nt][3] = 0.f;
    }
    const uint32_t aP  = sb + A_P + (qr0 + rowsel) * 272
                       + th * 128 + (lane >> 4) * 16;
    const uint32_t bV  = sb + A_VH + (th * 64 + rowsel) * 80 + (lane >> 4) * 16;
    const uint32_t bV2 = sb + A_VH + (th * 64 + rowsel) * 80 + 32;
    #pragma unroll
    for (int ks = 0; ks < 4; ks++) {
        uint32_t pa[4];
        ldsm_x4(pa, aP + ks * 32);
        uint32_t vh4[4], vl4[4], vh2[2], vl2[2];
        ldsm_x4_t(vh4, bV  + ks * 1280);
        ldsm_x2_t(vh2, bV2 + ks * 1280);
        ldsm_x4_t(vl4, bV  + 10240 + ks * 1280);
        ldsm_x2_t(vl2, bV2 + 10240 + ks * 1280);
        mma_f32acc(oh[0], pa, vh4[0], vh4[1]);
        mma_f32acc(oh[1], pa, vh4[2], vh4[3]);
        mma_f32acc(oh[2], pa, vh2[0], vh2[1]);
        mma_f32acc(ol[0], pa, vl4[0], vl4[1]);
        mma_f32acc(ol[1], pa, vl4[2], vl4[3]);
        mma_f32acc(ol[2], pa, vl2[0], vl2[1]);
    }

    // partial ctx -> smem (reuses Q region, dead after QK)
    {
        float* oc = (float*)smem + th * (64 * 20);
        #pragma unroll
        for (int nt = 0; nt < 3; nt++) {
            int c = nt * 8 + 2 * t;
            if (c < 20) {
                *(float2*)(oc + (qr0 + g) * 20 + c) = make_float2(
                    oh[nt][0] + ol[nt][0] * LO_INV,
                    oh[nt][1] + ol[nt][1] * LO_INV);
                *(float2*)(oc + (qr0 + 8 + g) * 20 + c) = make_float2(
                    oh[nt][2] + ol[nt][2] * LO_INV,
                    oh[nt][3] + ol[nt][3] * LO_INV);
            }
        }
    }
    __syncthreads();

    // combine key-halves, normalize, write ctx
    {
        float* oc0 = (float*)smem;
        float* oc1 = oc0 + 64 * 20;
        #pragma unroll
        for (int j = 0; j < 5; j++) {
            int idx = tid + j * 256;         // < 1280
            int r = idx / 20;
            int c = idx - r * 20;
            float denom = ps[r] + ps[64 + r];
            CTX[(qrow0 + r) * 200 + hoff + c] =
                (oc0[r * 20 + c] + oc1[r * 20 + c]) / denom;
        }
    }
}

// ---------------------------------------------------------------------------
extern "C" void kernel_launch(void* const* d_in, const int* in_sizes, int n_in,
                              void* d_out, int out_size) {
    const float* x  = (const float*)d_in[0];
    const float* wq = (const float*)d_in[1];
    const float* wk = (const float*)d_in[2];
    const float* wv = (const float*)d_in[3];

    float* attn = (float*)d_out;                       // 1024*10*128*128
    float* out  = (float*)d_out + 167772160L;          // 131072*200

    float* gctx;
    __half *h6, *whi, *wlo;
    cudaGetSymbolAddress((void**)&gctx, g_ctx);
    cudaGetSymbolAddress((void**)&h6,   g_h6);
    cudaGetSymbolAddress((void**)&whi,  g_whi);
    cudaGetSymbolAddress((void**)&wlo,  g_wlo);

    cudaFuncSetAttribute(gemm_mma, cudaFuncAttributeMaxDynamicSharedMemorySize,
                         GEMM_SMEM);
    cudaFuncSetAttribute(attn_mma, cudaFuncAttributeMaxDynamicSharedMemorySize,
                         ATT_SMEM);

    const int WSZ = 208 * 256;

    conv_wt3<<<dim3(208, 3), 256>>>(wq, wk, wv, whi, wlo);

    // Q/K/V projections -> fp16 hi/lo buffers
    gemm_mma<<<2048, 256, GEMM_SMEM>>>(x, whi + 0 * WSZ, wlo + 0 * WSZ,
                                       out, h6 + 0 * SZH, h6 + 1 * SZH, 1);
    gemm_mma<<<2048, 256, GEMM_SMEM>>>(x, whi + 1 * WSZ, wlo + 1 * WSZ,
                                       out, h6 + 2 * SZH, h6 + 3 * SZH, 1);
    gemm_mma<<<2048, 256, GEMM_SMEM>>>(x, whi + 2 * WSZ, wlo + 2 * WSZ,
                                       out, h6 + 4 * SZH, h6 + 5 * SZH, 1);

    attn_mma<<<dim3(1024, 10, 2), 256, ATT_SMEM>>>(h6, attn, gctx);

    // out = ctx @ Wq (fp32 epilogue)
    gemm_mma<<<2048, 256, GEMM_SMEM>>>(gctx, whi + 0 * WSZ, wlo + 0 * WSZ,
                                       out, h6, h6, 0);
}

// round 17
// speedup vs baseline: 1.4063x; 1.4063x over previous
#include <cuda_runtime.h>
#include <cuda_fp16.h>
#include <cstdint>

// ---------------------------------------------------------------------------
// MultiHeadSelfAttention: B=128,H=128,F=8,D=200, nh=10, hd=20
// Projections: mma.sync fp16 3-pass split GEMM; epilogue emits fp16 hi/lo
// Q/K/V (lo x2048) or fp32 (final out). Attention on tensor cores, block =
// (i, h, q-half): 64 q-rows, 256 thr, 2 blocks/SM (reg-cap 128, no spill).
// scale/ln2 folded into Wk.
// ---------------------------------------------------------------------------

typedef unsigned long long u64;

#define SZH (131072L * 200)

__device__ float  g_ctx[131072L * 200];
__device__ __half g_h6[6 * 131072L * 200];       // qh,ql,kh,kl,vh,vl
__device__ __half g_whi[3][208 * 256];
__device__ __half g_wlo[3][208 * 256];

#define LO_SCALE 2048.0f
#define LO_INV   (1.0f / 2048.0f)

// =========================== helpers =======================================
__device__ __forceinline__ void mma_f32acc(float* d, const uint32_t* a,
                                           uint32_t b0, uint32_t b1) {
    asm volatile(
        "mma.sync.aligned.m16n8k16.row.col.f32.f16.f16.f32 "
        "{%0,%1,%2,%3}, {%4,%5,%6,%7}, {%8,%9}, {%0,%1,%2,%3};"
        : "+f"(d[0]), "+f"(d[1]), "+f"(d[2]), "+f"(d[3])
        : "r"(a[0]), "r"(a[1]), "r"(a[2]), "r"(a[3]), "r"(b0), "r"(b1));
}
__device__ __forceinline__ void mma_f16acc(uint32_t* d, const uint32_t* a,
                                           uint32_t b0, uint32_t b1) {
    asm volatile(
        "mma.sync.aligned.m16n8k16.row.col.f16.f16.f16.f16 "
        "{%0,%1}, {%2,%3,%4,%5}, {%6,%7}, {%0,%1};"
        : "+r"(d[0]), "+r"(d[1])
        : "r"(a[0]), "r"(a[1]), "r"(a[2]), "r"(a[3]), "r"(b0), "r"(b1));
}
__device__ __forceinline__ void ldsm_x4(uint32_t* r, uint32_t addr) {
    asm volatile("ldmatrix.sync.aligned.m8n8.x4.shared.b16 {%0,%1,%2,%3}, [%4];"
        : "=r"(r[0]), "=r"(r[1]), "=r"(r[2]), "=r"(r[3]) : "r"(addr));
}
__device__ __forceinline__ void ldsm_x2(uint32_t* r, uint32_t addr) {
    asm volatile("ldmatrix.sync.aligned.m8n8.x2.shared.b16 {%0,%1}, [%2];"
        : "=r"(r[0]), "=r"(r[1]) : "r"(addr));
}
__device__ __forceinline__ void ldsm_x4_t(uint32_t* r, uint32_t addr) {
    asm volatile("ldmatrix.sync.aligned.m8n8.x4.trans.shared.b16 {%0,%1,%2,%3}, [%4];"
        : "=r"(r[0]), "=r"(r[1]), "=r"(r[2]), "=r"(r[3]) : "r"(addr));
}
__device__ __forceinline__ void ldsm_x2_t(uint32_t* r, uint32_t addr) {
    asm volatile("ldmatrix.sync.aligned.m8n8.x2.trans.shared.b16 {%0,%1}, [%2];"
        : "=r"(r[0]), "=r"(r[1]) : "r"(addr));
}
__device__ __forceinline__ uint32_t smem_u32(const void* p) {
    uint32_t a;
    asm("{ .reg .u64 t; cvta.to.shared.u64 t, %1; cvt.u32.u64 %0, t; }"
        : "=r"(a) : "l"(p));
    return a;
}
__device__ __forceinline__ void cp16(uint32_t dst, const void* src) {
    asm volatile("cp.async.ca.shared.global [%0], [%1], 16;"
                 :: "r"(dst), "l"(src) : "memory");
}
#define CP_COMMIT() asm volatile("cp.async.commit_group;" ::: "memory")
#define CP_WAIT0()  asm volatile("cp.async.wait_group 0;" ::: "memory")
__device__ __forceinline__ float ex2(float x) {
    float r; asm("ex2.approx.f32 %0, %1;" : "=f"(r) : "f"(x)); return r;
}

// ====== W{q,k,v} -> Wt[208][256] fp16 hi/lo (transpose+split), one launch ===
__global__ __launch_bounds__(256)
void conv_wt3(const float* __restrict__ wq, const float* __restrict__ wk,
              const float* __restrict__ wv, __half* __restrict__ hi,
              __half* __restrict__ lo) {
    const int w = blockIdx.y;
    const float* W = (w == 0) ? wq : (w == 1) ? wk : wv;
    const float s2 = 0.22360679774997896f / 0.6931471805599453f;
    int idx = blockIdx.x * 256 + threadIdx.x;     // over 208*256
    int n = idx >> 8, k = idx & 255;
    float v = (n < 200 && k < 200) ? W[k * 200 + n] : 0.f;
    if (w == 1) v *= s2;
    __half h = __float2half_rn(v);
    float r = (v - __half2float(h)) * LO_SCALE;
    hi[(long)w * (208 * 256) + idx] = h;
    lo[(long)w * (208 * 256) + idx] = __float2half_rn(r);
}

// ============ mma.sync fp16-split GEMM: 64x208 block, 2 blocks/SM ==========
#define AH_OFF 0
#define AL_OFF 9216
#define BH_OFF 18432
#define BL_OFF 48384
#define GEMM_SMEM 78336

__device__ __forceinline__ void load_a_chunk(const float* __restrict__ A,
                                             long row0, int tid, int kb,
                                             float4* abuf) {
    int r = tid >> 2, u4 = tid & 3;
    const float* ap = A + (row0 + r) * 200;
    #pragma unroll
    for (int q = 0; q < 4; q++) {
        int col0 = kb + u4 * 16 + q * 4;
        abuf[q] = (col0 < 200) ? *(const float4*)(ap + col0)
                               : make_float4(0.f, 0.f, 0.f, 0.f);
    }
}

__device__ __forceinline__ void conv_a_to_smem(char* smem, int tid,
                                               const float4* abuf) {
    int r = tid >> 2, u4 = tid & 3;
    char* ahp = smem + AH_OFF + r * 144 + u4 * 32;
    char* alp = smem + AL_OFF + r * 144 + u4 * 32;
    #pragma unroll
    for (int q = 0; q < 4; q++) {
        float4 v = abuf[q];
        __half2 h01 = __floats2half2_rn(v.x, v.y);
        __half2 h23 = __floats2half2_rn(v.z, v.w);
        float rx = (v.x - __low2float(h01))  * LO_SCALE;
        float ry = (v.y - __high2float(h01)) * LO_SCALE;
        float rz = (v.z - __low2float(h23))  * LO_SCALE;
        float rw = (v.w - __high2float(h23)) * LO_SCALE;
        __half2 l01 = __floats2half2_rn(rx, ry);
        __half2 l23 = __floats2half2_rn(rz, rw);
        *(uint32_t*)(ahp + q * 8)     = *(uint32_t*)&h01;
        *(uint32_t*)(ahp + q * 8 + 4) = *(uint32_t*)&h23;
        *(uint32_t*)(alp + q * 8)     = *(uint32_t*)&l01;
        *(uint32_t*)(alp + q * 8 + 4) = *(uint32_t*)&l23;
    }
}

__device__ __forceinline__ void issue_b_cpasync(uint32_t sbase, int tid,
                                                const __half* Bh,
                                                const __half* Bl, int kb) {
    #pragma unroll
    for (int i = 0; i < 13; i++) {
        int e = tid + i * 256;            // 0..3327
        int buf = e >= 1664;
        int e2 = buf ? e - 1664 : e;
        int n = e2 >> 3, u = e2 & 7;
        const __half* src = (buf ? Bl : Bh) + n * 256 + kb + u * 8;
        uint32_t dst = sbase + (buf ? BL_OFF : BH_OFF) + n * 144 + u * 16;
        cp16(dst, src);
    }
    CP_COMMIT();
}

__device__ __forceinline__ void mma_nt(float* accf, uint32_t* accc,
                                       const uint32_t* ah, const uint32_t* al,
                                       uint32_t bh0, uint32_t bh1,
                                       uint32_t bl0, uint32_t bl1) {
    mma_f32acc(accf, ah, bh0, bh1);
    mma_f16acc(accc, ah, bl0, bl1);
    mma_f16acc(accc, al, bh0, bh1);
}

// mode 0: write fp32 C. mode 1: write fp16 hi/lo (lo x2048) to Ch/Cl.
__global__ __launch_bounds__(256, 2)
void gemm_mma(const float* __restrict__ A,
              const __half* __restrict__ Bh,
              const __half* __restrict__ Bl,
              float* __restrict__ C,
              __half* __restrict__ Ch, __half* __restrict__ Cl,
              int mode) {
    extern __shared__ char smem[];
    const uint32_t sbase = smem_u32(smem);
    const int tid  = threadIdx.x;
    const int wid  = tid >> 5, lane = tid & 31;
    const int wm   = wid >> 1, wn = wid & 1;     // 4(M) x 2(N)
    const int g    = lane >> 2, t = lane & 3;
    const long row0 = (long)blockIdx.x * 64;

    const uint32_t aA = sbase + AH_OFF
        + (uint32_t)(wm * 16 + (lane & 15)) * 144 + (uint32_t)(lane >> 4) * 16;
    const uint32_t aB = sbase + BH_OFF
        + (uint32_t)(wn * 104 + (lane & 7) + ((lane >> 4) & 1) * 8) * 144
        + (uint32_t)((lane >> 3) & 1) * 16;

    float    accf[13][4];
    uint32_t accc[13][2];
    #pragma unroll
    for (int nt = 0; nt < 13; nt++) {
        accf[nt][0] = accf[nt][1] = accf[nt][2] = accf[nt][3] = 0.f;
        accc[nt][0] = accc[nt][1] = 0u;
    }

    float4 abuf[4];
    load_a_chunk(A, row0, tid, 0, abuf);
    issue_b_cpasync(sbase, tid, Bh, Bl, 0);
    conv_a_to_smem(smem, tid, abuf);
    CP_WAIT0();
    __syncthreads();

    #pragma unroll 1
    for (int c = 0; c < 4; c++) {
        if (c < 3) load_a_chunk(A, row0, tid, (c + 1) * 64, abuf);

        const int nst = (c < 3) ? 4 : 1;
        #pragma unroll 1
        for (int ks = 0; ks < nst; ks++) {
            const uint32_t ao = (uint32_t)ks * 32;
            uint32_t ah[4], al[4];
            ldsm_x4(ah, aA + ao);
            ldsm_x4(al, aA + 9216 + ao);
            #pragma unroll
            for (int p = 0; p < 6; p++) {
                uint32_t bh[4], bl[4];
                ldsm_x4(bh, aB + p * 2304 + ao);
                ldsm_x4(bl, aB + p * 2304 + 29952 + ao);
                mma_nt(accf[2 * p],     accc[2 * p],     ah, al,
                       bh[0], bh[1], bl[0], bl[1]);
                mma_nt(accf[2 * p + 1], accc[2 * p + 1], ah, al,
                       bh[2], bh[3], bl[2], bl[3]);
            }
            {
                uint32_t bh[2], bl[2];
                ldsm_x2(bh, aB + 13824 + ao);
                ldsm_x2(bl, aB + 13824 + 29952 + ao);
                mma_nt(accf[12], accc[12], ah, al,
                       bh[0], bh[1], bl[0], bl[1]);
            }
        }

        if (c < 3) {
            __syncthreads();
            issue_b_cpasync(sbase, tid, Bh, Bl, (c + 1) * 64);
            conv_a_to_smem(smem, tid, abuf);
            CP_WAIT0();
            __syncthreads();
        }
    }

    long r0 = row0 + wm * 16 + g;
    #pragma unroll
    for (int nt = 0; nt < 13; nt++) {
        int col = wn * 104 + nt * 8 + t * 2;
        if (col < 200) {
            __half2 h0 = *(__half2*)&accc[nt][0];
            __half2 h1 = *(__half2*)&accc[nt][1];
            float v0 = accf[nt][0] + __low2float(h0)  * LO_INV;
            float v1 = accf[nt][1] + __high2float(h0) * LO_INV;
            float v2 = accf[nt][2] + __low2float(h1)  * LO_INV;
            float v3 = accf[nt][3] + __high2float(h1) * LO_INV;
            if (mode == 0) {
                *(float2*)(C + r0 * 200 + col)       = make_float2(v0, v1);
                *(float2*)(C + (r0 + 8) * 200 + col) = make_float2(v2, v3);
            } else {
                __half2 hh0 = __floats2half2_rn(v0, v1);
                __half2 hh1 = __floats2half2_rn(v2, v3);
                __half2 ll0 = __floats2half2_rn(
                    (v0 - __low2float(hh0))  * LO_SCALE,
                    (v1 - __high2float(hh0)) * LO_SCALE);
                __half2 ll1 = __floats2half2_rn(
                    (v2 - __low2float(hh1))  * LO_SCALE,
                    (v3 - __high2float(hh1)) * LO_SCALE);
                *(__half2*)(Ch + r0 * 200 + col)       = hh0;
                *(__half2*)(Ch + (r0 + 8) * 200 + col) = hh1;
                *(__half2*)(Cl + r0 * 200 + col)       = ll0;
                *(__half2*)(Cl + (r0 + 8) * 200 + col) = ll1;
            }
        }
    }
}

// ============== Tensor-core attention per (i, h, q-half) ====================
// 256 threads = 8 warps; warp = (qr0 = (wid>>1)*16 of 64 q-rows) x (key-half).
// 2 blocks/SM (reg cap 128 -> no spills; this was the R16 bug at occ 3).
#define A_QH 0
#define A_QL 5120
#define A_KH 10240
#define A_KL 20480
#define A_VH 30720
#define A_VL 40960
#define A_P  51200
#define A_PS 68608
#define ATT_SMEM 69120

__global__ __launch_bounds__(256, 2)
void attn_mma(const __half* __restrict__ H6, float* __restrict__ AW,
              float* __restrict__ CTX) {
    extern __shared__ char smem[];
    const uint32_t sb = smem_u32(smem);
    const int tid  = threadIdx.x;
    const int lane = tid & 31, wid = tid >> 5;
    const int g = lane >> 2, t = lane & 3;
    const int qr0 = (wid >> 1) * 16;
    const int th  = wid & 1;
    const long rb = (long)blockIdx.x * 128;
    const int hoff = blockIdx.y * 20;
    const long qrow0 = rb + blockIdx.z * 64;

    // ---- load Q (64 rows) + K/V (128 rows) hi/lo slices ----
    #pragma unroll
    for (int rr = 0; rr < 3; rr++) {
        int tau = tid + rr * 256;
        if (tau < 640) {
            const u64* src;
            u64* dst;
            if (tau < 128) {
                int buf = tau >> 6, r = tau & 63;        // QH, QL
                src = (const u64*)(H6 + (long)buf * SZH + (qrow0 + r) * 200 + hoff);
                dst = (u64*)(smem + buf * 5120 + r * 80);
            } else {
                int tau2 = tau - 128;
                int buf = tau2 >> 7, r = tau2 & 127;     // KH,KL,VH,VL
                src = (const u64*)(H6 + (long)(buf + 2) * SZH + (rb + r) * 200 + hoff);
                dst = (u64*)(smem + A_KH + buf * 10240 + r * 80);
            }
            dst[0] = src[0]; dst[1] = src[1]; dst[2] = src[2];
            dst[3] = src[3]; dst[4] = src[4];
            dst[5] = 0; dst[6] = 0; dst[7] = 0;          // zero-pad d20..31
        }
    }
    __syncthreads();

    const uint32_t rowsel = ((lane >> 3) & 1) * 8 + (lane & 7);

    // ---------------- QK^T: 3-pass fp16 split ----------------
    const uint32_t aQ = sb + A_QH + (qr0 + rowsel) * 80 + (lane >> 4) * 16;
    const uint32_t bK = sb + A_KH
        + (th * 64 + ((lane >> 4) & 1) * 8 + (lane & 7)) * 80
        + ((lane >> 3) & 1) * 16;

    float    accf[8][4];
    uint32_t corr[8][2];
    #pragma unroll
    for (int nt = 0; nt < 8; nt++) {
        accf[nt][0] = accf[nt][1] = accf[nt][2] = accf[nt][3] = 0.f;
        corr[nt][0] = corr[nt][1] = 0u;
    }
    #pragma unroll
    for (int ks = 0; ks < 2; ks++) {
        uint32_t ah[4], al[4];
        ldsm_x4(ah, aQ + ks * 32);
        ldsm_x4(al, aQ + 5120 + ks * 32);
        #pragma unroll
        for (int p = 0; p < 4; p++) {
            uint32_t bh[4], bl[4];
            ldsm_x4(bh, bK + p * 1280 + ks * 32);
            ldsm_x4(bl, bK + 10240 + p * 1280 + ks * 32);
            mma_f32acc(accf[2 * p],     ah, bh[0], bh[1]);
            mma_f16acc(corr[2 * p],     ah, bl[0], bl[1]);
            mma_f16acc(corr[2 * p],     al, bh[0], bh[1]);
            mma_f32acc(accf[2 * p + 1], ah, bh[2], bh[3]);
            mma_f16acc(corr[2 * p + 1], ah, bl[2], bl[3]);
            mma_f16acc(corr[2 * p + 1], al, bh[2], bh[3]);
        }
    }

    // ---------------- exp, P->smem(fp16), row sums ----------------
    float sum_a = 0.f, sum_b = 0.f;
    char* pst = smem + A_P + (qr0 + g) * 272 + (th * 64 + 2 * t) * 2;
    #pragma unroll
    for (int nt = 0; nt < 8; nt++) {
        __half2 c0 = *(__half2*)&corr[nt][0];
        __half2 c1 = *(__half2*)&corr[nt][1];
        float e0 = ex2(accf[nt][0] + __low2float(c0)  * LO_INV);
        float e1 = ex2(accf[nt][1] + __high2float(c0) * LO_INV);
        float e2 = ex2(accf[nt][2] + __low2float(c1)  * LO_INV);
        float e3 = ex2(accf[nt][3] + __high2float(c1) * LO_INV);
        sum_a += e0 + e1; sum_b += e2 + e3;
        __half2 p01 = __floats2half2_rn(e0, e1);
        __half2 p23 = __floats2half2_rn(e2, e3);
        *(uint32_t*)(pst + nt * 16)           = *(uint32_t*)&p01;
        *(uint32_t*)(pst + 8 * 272 + nt * 16) = *(uint32_t*)&p23;
    }
    sum_a += __shfl_xor_sync(0xffffffffu, sum_a, 1);
    sum_a += __shfl_xor_sync(0xffffffffu, sum_a, 2);
    sum_b += __shfl_xor_sync(0xffffffffu, sum_b, 1);
    sum_b += __shfl_xor_sync(0xffffffffu, sum_b, 2);
    float* ps = (float*)(smem + A_PS);
    if (t == 0) {
        ps[th * 64 + qr0 + g]     = sum_a;
        ps[th * 64 + qr0 + 8 + g] = sum_b;
    }
    __syncthreads();

    // ---------------- AW write: cooperative, coalesced ----------------
    {
        float4* aw4 = (float4*)(AW + ((long)blockIdx.x * 10 + blockIdx.y) * 16384
                                   + (long)blockIdx.z * 8192);
        #pragma unroll
        for (int e0 = 0; e0 < 8; e0++) {
            int e = tid + e0 * 256;
            int s = e >> 5, l = e & 31;
            uint32_t pv[2];
            *(u64*)pv = *(const u64*)(smem + A_P + s * 272 + l * 8);
            __half2 p01 = *(__half2*)&pv[0];
            __half2 p23 = *(__half2*)&pv[1];
            float inv = 1.0f / (ps[s] + ps[64 + s]);
            aw4[e] = make_float4(__low2float(p01) * inv, __high2float(p01) * inv,
                                 __low2float(p23) * inv, __high2float(p23) * inv);
        }
    }

    // ---------------- AV: P(fp16) @ (Vh + Vl/2048) ----------------
    float oh[3][4], ol[3][4];
    #pragma unroll
    for (int nt = 0; nt < 3; nt++) {
        oh[nt][0] = oh[nt][1] = oh[nt][2] = oh[nt][3] = 0.f;
        ol[nt][0] = ol[nt][1] = ol[nt][2] = ol[nt][3] = 0.f;
    }
    const uint32_t aP  = sb + A_P + (qr0 + rowsel) * 272
                       + th * 128 + (lane >> 4) * 16;
    const uint32_t bV  = sb + A_VH + (th * 64 + rowsel) * 80 + (lane >> 4) * 16;
    const uint32_t bV2 = sb + A_VH + (th * 64 + rowsel) * 80 + 32;
    #pragma unroll
    for (int ks = 0; ks < 4; ks++) {
        uint32_t pa[4];
        ldsm_x4(pa, aP + ks * 32);
        uint32_t vh4[4], vl4[4], vh2[2], vl2[2];
        ldsm_x4_t(vh4, bV  + ks * 1280);
        ldsm_x2_t(vh2, bV2 + ks * 1280);
        ldsm_x4_t(vl4, bV  + 10240 + ks * 1280);
        ldsm_x2_t(vl2, bV2 + 10240 + ks * 1280);
        mma_f32acc(oh[0], pa, vh4[0], vh4[1]);
        mma_f32acc(oh[1], pa, vh4[2], vh4[3]);
        mma_f32acc(oh[2], pa, vh2[0], vh2[1]);
        mma_f32acc(ol[0], pa, vl4[0], vl4[1]);
        mma_f32acc(ol[1], pa, vl4[2], vl4[3]);
        mma_f32acc(ol[2], pa, vl2[0], vl2[1]);
    }

    // partial ctx -> smem (reuses Q region, dead after QK)
    {
        float* oc = (float*)smem + th * (64 * 20);
        #pragma unroll
        for (int nt = 0; nt < 3; nt++) {
            int c = nt * 8 + 2 * t;
            if (c < 20) {
                *(float2*)(oc + (qr0 + g) * 20 + c) = make_float2(
                    oh[nt][0] + ol[nt][0] * LO_INV,
                    oh[nt][1] + ol[nt][1] * LO_INV);
                *(float2*)(oc + (qr0 + 8 + g) * 20 + c) = make_float2(
                    oh[nt][2] + ol[nt][2] * LO_INV,
                    oh[nt][3] + ol[nt][3] * LO_INV);
            }
        }
    }
    __syncthreads();

    // combine key-halves, normalize, write ctx
    {
        float* oc0 = (float*)smem;
        float* oc1 = oc0 + 64 * 20;
        #pragma unroll
        for (int j = 0; j < 5; j++) {
            int idx = tid + j * 256;         // < 1280
            int r = idx / 20;
            int c = idx - r * 20;
            float denom = ps[r] + ps[64 + r];
            CTX[(qrow0 + r) * 200 + hoff + c] =
                (oc0[r * 20 + c] + oc1[r * 20 + c]) / denom;
        }
    }
}

// ---------------------------------------------------------------------------
extern "C" void kernel_launch(void* const* d_in, const int* in_sizes, int n_in,
                              void* d_out, int out_size) {
    const float* x  = (const float*)d_in[0];
    const float* wq = (const float*)d_in[1];
    const float* wk = (const float*)d_in[2];
    const float* wv = (const float*)d_in[3];

    float* attn = (float*)d_out;                       // 1024*10*128*128
    float* out  = (float*)d_out + 167772160L;          // 131072*200

    float* gctx;
    __half *h6, *whi, *wlo;
    cudaGetSymbolAddress((void**)&gctx, g_ctx);
    cudaGetSymbolAddress((void**)&h6,   g_h6);
    cudaGetSymbolAddress((void**)&whi,  g_whi);
    cudaGetSymbolAddress((void**)&wlo,  g_wlo);

    cudaFuncSetAttribute(gemm_mma, cudaFuncAttributeMaxDynamicSharedMemorySize,
                         GEMM_SMEM);
    cudaFuncSetAttribute(attn_mma, cudaFuncAttributeMaxDynamicSharedMemorySize,
                         ATT_SMEM);

    const int WSZ = 208 * 256;

    conv_wt3<<<dim3(208, 3), 256>>>(wq, wk, wv, whi, wlo);

    // Q/K/V projections -> fp16 hi/lo buffers
    gemm_mma<<<2048, 256, GEMM_SMEM>>>(x, whi + 0 * WSZ, wlo + 0 * WSZ,
                                       out, h6 + 0 * SZH, h6 + 1 * SZH, 1);
    gemm_mma<<<2048, 256, GEMM_SMEM>>>(x, whi + 1 * WSZ, wlo + 1 * WSZ,
                                       out, h6 + 2 * SZH, h6 + 3 * SZH, 1);
    gemm_mma<<<2048, 256, GEMM_SMEM>>>(x, whi + 2 * WSZ, wlo + 2 * WSZ,
                                       out, h6 + 4 * SZH, h6 + 5 * SZH, 1);

    attn_mma<<<dim3(1024, 10, 2), 256, ATT_SMEM>>>(h6, attn, gctx);

    // out = ctx @ Wq (fp32 epilogue)
    gemm_mma<<<2048, 256, GEMM_SMEM>>>(gctx, whi + 0 * WSZ, wlo + 0 * WSZ,
                                       out, h6, h6, 0);
}